// round 2
// baseline (speedup 1.0000x reference)
#include <cuda_runtime.h>
#include <cstdint>
#include <cstddef>

#define N_NODES  100000
#define N_EDGES  3200000
#define FEAT     128
#define NUM_RELS 16
#define NUM_BASES 8

// Scratch (static device globals — no runtime allocation allowed).
__device__ float g_xb[(size_t)NUM_BASES * N_NODES * FEAT];   // 410 MB: xb[b][n][o]
__device__ float g_h [(size_t)NUM_RELS  * N_NODES * FEAT];   // 819 MB: h[r][n][o]
__device__ int   g_idx64;                                    // 1 if indices are int64

// ---------------------------------------------------------------------------
// Probe: decide whether index arrays are int64 or int32.
// If data is int32, reading as int64 packs two int32s; the high word is the
// next (random, almost surely nonzero) value -> out-of-range detection.
// ---------------------------------------------------------------------------
__global__ void probe_kernel(const void* src) {
    if (blockIdx.x == 0 && threadIdx.x == 0) {
        const long long* p = (const long long*)src;
        int is64 = 1;
        for (int i = 0; i < 1024; i++) {
            long long v = p[i];
            if (v < 0 || v >= (long long)N_NODES) { is64 = 0; break; }
        }
        g_idx64 = is64;
    }
}

// ---------------------------------------------------------------------------
// K1: xb[b] = x @ weight[b]   (M=100000, N=128, K=128), 8 bases via grid.y
// Tiling: BM=128, BN=128, BK=8; 256 threads; 8x8 register micro-tile.
// ---------------------------------------------------------------------------
__global__ __launch_bounds__(256) void xb_gemm(const float* __restrict__ x,
                                               const float* __restrict__ w) {
    const int b  = blockIdx.y;
    const int m0 = blockIdx.x * 128;

    __shared__ float As[8][132];   // [k][m], padded row (528B, 16B-aligned)
    __shared__ float Bs[8][128];   // [k][n]

    const int tid = threadIdx.x;
    const int tx  = tid & 15;      // 0..15 -> N
    const int ty  = tid >> 4;      // 0..15 -> M

    float acc[8][8];
#pragma unroll
    for (int i = 0; i < 8; i++)
#pragma unroll
        for (int j = 0; j < 8; j++) acc[i][j] = 0.f;

    const int arow  = tid >> 1;         // 0..127
    const int apart = (tid & 1) * 4;    // 0 or 4 (k sub-chunk)
    const int brow  = tid >> 5;         // 0..7
    const int bcol  = (tid & 31) * 4;   // 0..124
    const float* wb = w + (size_t)b * FEAT * FEAT;
    const bool arow_ok = (m0 + arow) < N_NODES;

    for (int kk = 0; kk < FEAT; kk += 8) {
        float4 av = make_float4(0.f, 0.f, 0.f, 0.f);
        if (arow_ok)
            av = *(const float4*)(x + (size_t)(m0 + arow) * FEAT + kk + apart);
        As[apart + 0][arow] = av.x;
        As[apart + 1][arow] = av.y;
        As[apart + 2][arow] = av.z;
        As[apart + 3][arow] = av.w;
        *(float4*)(&Bs[brow][bcol]) =
            *(const float4*)(wb + (size_t)(kk + brow) * FEAT + bcol);
        __syncthreads();

#pragma unroll
        for (int k = 0; k < 8; k++) {
            float4 a0 = *(const float4*)(&As[k][ty * 8]);
            float4 a1 = *(const float4*)(&As[k][ty * 8 + 4]);
            float4 b0 = *(const float4*)(&Bs[k][tx * 8]);
            float4 b1 = *(const float4*)(&Bs[k][tx * 8 + 4]);
            float ar[8] = {a0.x, a0.y, a0.z, a0.w, a1.x, a1.y, a1.z, a1.w};
            float br[8] = {b0.x, b0.y, b0.z, b0.w, b1.x, b1.y, b1.z, b1.w};
#pragma unroll
            for (int i = 0; i < 8; i++)
#pragma unroll
                for (int j = 0; j < 8; j++)
                    acc[i][j] += ar[i] * br[j];
        }
        __syncthreads();
    }

    float* outb = g_xb + (size_t)b * N_NODES * FEAT;
#pragma unroll
    for (int i = 0; i < 8; i++) {
        int row = m0 + ty * 8 + i;
        if (row < N_NODES) {
            *(float4*)(outb + (size_t)row * FEAT + tx * 8) =
                make_float4(acc[i][0], acc[i][1], acc[i][2], acc[i][3]);
            *(float4*)(outb + (size_t)row * FEAT + tx * 8 + 4) =
                make_float4(acc[i][4], acc[i][5], acc[i][6], acc[i][7]);
        }
    }
}

// ---------------------------------------------------------------------------
// K2: h[r][n][o] = sum_b w_comp[r][b] * xb[b][n][o]   (streaming, float4)
// ---------------------------------------------------------------------------
__global__ __launch_bounds__(256) void combine_kernel(const float* __restrict__ w_comp) {
    __shared__ float c[NUM_RELS * NUM_BASES];
    if (threadIdx.x < NUM_RELS * NUM_BASES)
        c[threadIdx.x] = w_comp[threadIdx.x];
    __syncthreads();

    size_t t = (size_t)blockIdx.x * blockDim.x + threadIdx.x;  // float4 index
    const size_t total = (size_t)N_NODES * (FEAT / 4);
    if (t >= total) return;

    const float4* xb4 = (const float4*)g_xb;
    float4 xv[NUM_BASES];
#pragma unroll
    for (int b = 0; b < NUM_BASES; b++)
        xv[b] = xb4[(size_t)b * total + t];

    float4* h4 = (float4*)g_h;
#pragma unroll
    for (int r = 0; r < NUM_RELS; r++) {
        float4 acc = make_float4(0.f, 0.f, 0.f, 0.f);
#pragma unroll
        for (int b = 0; b < NUM_BASES; b++) {
            float s = c[r * NUM_BASES + b];
            acc.x += s * xv[b].x;
            acc.y += s * xv[b].y;
            acc.z += s * xv[b].z;
            acc.w += s * xv[b].w;
        }
        h4[(size_t)r * total + t] = acc;
    }
}

// ---------------------------------------------------------------------------
// K3a: out[n][o] = h_bias[o]  (out is poisoned by harness; must init)
// ---------------------------------------------------------------------------
__global__ __launch_bounds__(256) void init_out(float4* __restrict__ out,
                                                const float4* __restrict__ bias) {
    size_t t = (size_t)blockIdx.x * blockDim.x + threadIdx.x;
    const size_t total = (size_t)N_NODES * (FEAT / 4);
    if (t < total) out[t] = bias[t & 31];
}

// ---------------------------------------------------------------------------
// K3b: per edge, gather h[etype][src] and red.add into out[dst].
// One warp handles 4 edges (row = 32 lanes x float4 = 512B). Loads batched
// for MLP, then reductions issued.
// ---------------------------------------------------------------------------
#define EDGES_PER_WARP 4
__global__ __launch_bounds__(256) void edge_kernel(const void* __restrict__ srcp,
                                                   const void* __restrict__ dstp,
                                                   const void* __restrict__ etp,
                                                   float* __restrict__ out) {
    const int warp = threadIdx.x >> 5;
    const int lane = threadIdx.x & 31;
    const int e0 = (blockIdx.x * 8 + warp) * EDGES_PER_WARP;
    if (e0 >= N_EDGES) return;
    const int idx64 = g_idx64;

    float4 v[EDGES_PER_WARP];
    float4* op[EDGES_PER_WARP];
    int valid[EDGES_PER_WARP];

#pragma unroll
    for (int q = 0; q < EDGES_PER_WARP; q++) {
        int e = e0 + q;
        valid[q] = (e < N_EDGES);
        if (valid[q]) {
            long long s, d, r;
            if (idx64) {
                s = ((const long long*)srcp)[e];
                d = ((const long long*)dstp)[e];
                r = ((const long long*)etp)[e];
            } else {
                s = ((const int*)srcp)[e];
                d = ((const int*)dstp)[e];
                r = ((const int*)etp)[e];
            }
            const float4* hp = (const float4*)g_h +
                               ((size_t)r * N_NODES + (size_t)s) * (FEAT / 4);
            v[q]  = hp[lane];
            op[q] = (float4*)out + (size_t)d * (FEAT / 4) + lane;
        }
    }

#pragma unroll
    for (int q = 0; q < EDGES_PER_WARP; q++) {
        if (valid[q]) {
            asm volatile("red.global.add.v4.f32 [%0], {%1, %2, %3, %4};"
                         :: "l"(op[q]), "f"(v[q].x), "f"(v[q].y),
                            "f"(v[q].z), "f"(v[q].w)
                         : "memory");
        }
    }
}

// ---------------------------------------------------------------------------
// Launch
// ---------------------------------------------------------------------------
extern "C" void kernel_launch(void* const* d_in, const int* in_sizes, int n_in,
                              void* d_out, int out_size) {
    const float* x      = (const float*)d_in[0];
    const float* weight = (const float*)d_in[1];
    const float* w_comp = (const float*)d_in[2];
    const float* h_bias = (const float*)d_in[3];
    const void*  src    = d_in[4];
    const void*  dst    = d_in[5];
    const void*  etyp   = d_in[6];
    float*       out    = (float*)d_out;

    probe_kernel<<<1, 1>>>(src);

    dim3 g1((N_NODES + 127) / 128, NUM_BASES);
    xb_gemm<<<g1, 256>>>(x, weight);

    const int total4 = N_NODES * (FEAT / 4);  // 3.2M float4
    combine_kernel<<<(total4 + 255) / 256, 256>>>(w_comp);
    init_out<<<(total4 + 255) / 256, 256>>>((float4*)out, (const float4*)h_bias);

    const int warps_needed = (N_EDGES + EDGES_PER_WARP - 1) / EDGES_PER_WARP;
    edge_kernel<<<(warps_needed + 7) / 8, 256>>>(src, dst, etyp, out);
}